// round 2
// baseline (speedup 1.0000x reference)
#include <cuda_runtime.h>
#include <cstdint>
#include <cstddef>

static constexpr int BATCH = 4;
static constexpr int SEQ   = 4096;
static constexpr int DIM   = 1024;
static constexpr int RANK  = 32;

// Scratch (device globals: allocation-free per harness rules)
__device__ float g_xr  [(size_t)BATCH*SEQ*DIM];   // tf32-rounded x           (64 MB)
__device__ float g_qk  [64*DIM];                  // concat [Q;K] rounded
__device__ float g_vor [DIM*DIM];                 // rounded VO
__device__ float g_xqk [(size_t)BATCH*SEQ*64];    // [b][t][0:32]=xq [32:64]=xk
__device__ float g_attn[(size_t)BATCH*SEQ*SEQ];   // scores -> attn           (256 MB)
__device__ float g_ctx [(size_t)BATCH*SEQ*DIM];   // attn @ x                 (64 MB)

__device__ __forceinline__ float tf32r(float x){
    uint32_t u; asm("cvt.rna.tf32.f32 %0, %1;" : "=r"(u) : "f"(x));
    return __uint_as_float(u);
}

__global__ void __launch_bounds__(256) round_kernel(const float* __restrict__ in,
                                                    float* __restrict__ out, int n4){
    int i = blockIdx.x*blockDim.x + threadIdx.x;
    int stride = gridDim.x*blockDim.x;
    for (; i < n4; i += stride){
        float4 v = ((const float4*)in)[i];
        v.x = tf32r(v.x); v.y = tf32r(v.y); v.z = tf32r(v.z); v.w = tf32r(v.w);
        ((float4*)out)[i] = v;
    }
}

__device__ __forceinline__ void mma_tf32(float* c, const uint32_t* a, const uint32_t* b){
    asm volatile(
        "mma.sync.aligned.m16n8k8.row.col.f32.tf32.tf32.f32 "
        "{%0,%1,%2,%3}, {%4,%5,%6,%7}, {%8,%9}, {%0,%1,%2,%3};\n"
        : "+f"(c[0]), "+f"(c[1]), "+f"(c[2]), "+f"(c[3])
        : "r"(a[0]), "r"(a[1]), "r"(a[2]), "r"(a[3]), "r"(b[0]), "r"(b[1]));
}

__device__ __forceinline__ void cp16(uint32_t s, const void* g){
    asm volatile("cp.async.ca.shared.global [%0], [%1], 16;\n" :: "r"(s), "l"(g));
}

// C[M,N] = alpha * A[M,K] * op(B). BT=true: B is [N,K] row-major (NT GEMM).
// BT=false: B is [K,N] row-major (NN GEMM). All dims divide tiles exactly.
// grid = (N/BN, M/BM, batch). 256 threads = 8 warps in 2x4 layout.
template<int BM, int BN, int BK, bool BT, bool ROUND>
__global__ void __launch_bounds__(256,1)
gemm_tf32(const float* __restrict__ Agp, const float* __restrict__ Bgp,
          float* __restrict__ Cgp, int K, int lda, int ldb, int ldc,
          size_t strA, size_t strB, size_t strC, float alpha)
{
    constexpr int PA  = BK + 4;                 // padded A/B-NT row stride
    constexpr int PB  = BN + 4;                 // padded B-NN row stride
    constexpr int WM  = BM/2, WN = BN/4;
    constexpr int MF  = WM/16, NF = WN/8;
    constexpr int ASZ = BM*PA;
    constexpr int BSZ = BT ? BN*PA : BK*PB;

    __shared__ float sA[2*ASZ];
    __shared__ float sB[2*BSZ];

    const float* Ag = Agp + blockIdx.z*strA + (size_t)blockIdx.y*BM*lda;
    const float* Bg = Bgp + blockIdx.z*strB +
                      (BT ? (size_t)blockIdx.x*BN*ldb : (size_t)blockIdx.x*BN);
    float* Cg = Cgp + blockIdx.z*strC + (size_t)blockIdx.y*BM*ldc + (size_t)blockIdx.x*BN;

    const int tid  = threadIdx.x;
    const int warp = tid >> 5, lane = tid & 31;
    const int wm   = warp >> 2, wn = warp & 3;
    const int grp  = lane >> 2, tig = lane & 3;

    const uint32_t sAb = (uint32_t)__cvta_generic_to_shared(sA);
    const uint32_t sBb = (uint32_t)__cvta_generic_to_shared(sB);

    float acc[MF][NF][4];
    #pragma unroll
    for (int i=0;i<MF;i++)
        #pragma unroll
        for (int j=0;j<NF;j++)
            #pragma unroll
            for (int q=0;q<4;q++) acc[i][j][q] = 0.f;

    const int KT = K / BK;

    // A tile: BM rows x BK floats; BK/4 float4 per row
    constexpr int AFR   = BK/4;
    constexpr int ARP   = 256/AFR;
    constexpr int APASS = BM/ARP;
    const int a_r = tid / AFR;
    const int a_c = (tid % AFR) * 4;
    // B-NT: BN rows x BK floats (same row mapping as A)
    constexpr int BTPASS = (BN/ARP > 0) ? BN/ARP : 1;
    // B-NN: BK rows x BN floats
    constexpr int NFR   = BN/4;
    constexpr int NRP   = 256/NFR;
    constexpr int NPASS = BK/NRP;
    const int b_r = tid / NFR;
    const int b_c = (tid % NFR) * 4;

    auto load_tile = [&](int kt, int buf){
        const float* Ak = Ag + kt*BK;
        #pragma unroll
        for (int p=0;p<APASS;p++){
            int r = a_r + p*ARP;
            cp16(sAb + (uint32_t)(buf*ASZ + r*PA + a_c)*4u, Ak + (size_t)r*lda + a_c);
        }
        if constexpr (BT) {
            const float* Bk = Bg + kt*BK;
            #pragma unroll
            for (int p=0;p<BTPASS;p++){
                int r = a_r + p*ARP;
                cp16(sBb + (uint32_t)(buf*BSZ + r*PA + a_c)*4u, Bk + (size_t)r*ldb + a_c);
            }
        } else {
            const float* Bk = Bg + (size_t)kt*BK*ldb;
            #pragma unroll
            for (int p=0;p<NPASS;p++){
                int r = b_r + p*NRP;
                cp16(sBb + (uint32_t)(buf*BSZ + r*PB + b_c)*4u, Bk + (size_t)r*ldb + b_c);
            }
        }
    };

    auto compute = [&](int buf){
        const float* cA = sA + buf*ASZ;
        const float* cB = sB + buf*BSZ;
        #pragma unroll
        for (int k8=0; k8<BK/8; k8++){
            uint32_t af[MF][4], bf[NF][2];
            #pragma unroll
            for (int mf=0; mf<MF; mf++){
                int r = wm*WM + mf*16 + grp;
                const float* base = cA + r*PA + k8*8 + tig;
                af[mf][0] = __float_as_uint(base[0]);
                af[mf][1] = __float_as_uint(base[8*PA]);
                af[mf][2] = __float_as_uint(base[4]);
                af[mf][3] = __float_as_uint(base[8*PA+4]);
            }
            #pragma unroll
            for (int nf=0; nf<NF; nf++){
                int n = wn*WN + nf*8 + grp;
                if constexpr (BT) {
                    const float* base = cB + n*PA + k8*8 + tig;
                    bf[nf][0] = __float_as_uint(base[0]);
                    bf[nf][1] = __float_as_uint(base[4]);
                } else {
                    const float* base = cB + (k8*8+tig)*PB + n;
                    bf[nf][0] = __float_as_uint(base[0]);
                    bf[nf][1] = __float_as_uint(base[4*PB]);
                }
            }
            #pragma unroll
            for (int mf=0; mf<MF; mf++)
                #pragma unroll
                for (int nf=0; nf<NF; nf++)
                    mma_tf32(acc[mf][nf], af[mf], bf[nf]);
        }
    };

    load_tile(0, 0);
    asm volatile("cp.async.commit_group;\n");
    for (int kt=0; kt<KT; kt++){
        if (kt+1 < KT){
            load_tile(kt+1, (kt+1)&1);
            asm volatile("cp.async.commit_group;\n");
            asm volatile("cp.async.wait_group 1;\n");
        } else {
            asm volatile("cp.async.wait_group 0;\n");
        }
        __syncthreads();
        compute(kt&1);
        __syncthreads();
    }

    #pragma unroll
    for (int mf=0; mf<MF; mf++){
        int r = wm*WM + mf*16 + grp;
        #pragma unroll
        for (int nf=0; nf<NF; nf++){
            int c = wn*WN + nf*8 + tig*2;
            float2 v0, v1;
            v0.x = alpha*acc[mf][nf][0]; v0.y = alpha*acc[mf][nf][1];
            v1.x = alpha*acc[mf][nf][2]; v1.y = alpha*acc[mf][nf][3];
            if (ROUND){
                v0.x = tf32r(v0.x); v0.y = tf32r(v0.y);
                v1.x = tf32r(v1.x); v1.y = tf32r(v1.y);
            }
            *(float2*)(Cg + (size_t)r*ldc + c)     = v0;
            *(float2*)(Cg + (size_t)(r+8)*ldc + c) = v1;
        }
    }
}

// One block per row of 4096: load->max->exp->sum->normalize (tf32-rounded output)
__global__ void __launch_bounds__(256,1) softmax_rows(float* __restrict__ attn){
    float* p = attn + (size_t)blockIdx.x * SEQ;
    const int t = threadIdx.x;
    float4 v[4];
    float m = -3.4e38f;
    #pragma unroll
    for (int i=0;i<4;i++){
        v[i] = ((const float4*)p)[t + 256*i];
        m = fmaxf(m, fmaxf(fmaxf(v[i].x, v[i].y), fmaxf(v[i].z, v[i].w)));
    }
    __shared__ float red[8];
    #pragma unroll
    for (int o=16;o>0;o>>=1) m = fmaxf(m, __shfl_xor_sync(0xffffffffu, m, o));
    if ((t&31)==0) red[t>>5] = m;
    __syncthreads();
    float M = red[0];
    #pragma unroll
    for (int i=1;i<8;i++) M = fmaxf(M, red[i]);
    float s = 0.f;
    #pragma unroll
    for (int i=0;i<4;i++){
        v[i].x = __expf(v[i].x - M); v[i].y = __expf(v[i].y - M);
        v[i].z = __expf(v[i].z - M); v[i].w = __expf(v[i].w - M);
        s += (v[i].x + v[i].y) + (v[i].z + v[i].w);
    }
    #pragma unroll
    for (int o=16;o>0;o>>=1) s += __shfl_xor_sync(0xffffffffu, s, o);
    __syncthreads();                   // red[] (M) reads done before reuse
    if ((t&31)==0) red[t>>5] = s;
    __syncthreads();
    float S = red[0];
    #pragma unroll
    for (int i=1;i<8;i++) S += red[i];
    float inv = __fdividef(1.f, S);
    #pragma unroll
    for (int i=0;i<4;i++){
        v[i].x = tf32r(v[i].x*inv); v[i].y = tf32r(v[i].y*inv);
        v[i].z = tf32r(v[i].z*inv); v[i].w = tf32r(v[i].w*inv);
        ((float4*)p)[t + 256*i] = v[i];
    }
}

extern "C" void kernel_launch(void* const* d_in, const int* in_sizes, int n_in,
                              void* d_out, int out_size){
    const float* x  = (const float*)d_in[0];
    const float* Q  = (const float*)d_in[1];
    const float* Km = (const float*)d_in[2];
    const float* VO = (const float*)d_in[3];
    float* out = (float*)d_out;

    float *xr, *qk, *vor, *xqk, *attn, *ctx;
    cudaGetSymbolAddress((void**)&xr,   g_xr);
    cudaGetSymbolAddress((void**)&qk,   g_qk);
    cudaGetSymbolAddress((void**)&vor,  g_vor);
    cudaGetSymbolAddress((void**)&xqk,  g_xqk);
    cudaGetSymbolAddress((void**)&attn, g_attn);
    cudaGetSymbolAddress((void**)&ctx,  g_ctx);

    // 1) TF32 pre-rounding (removes CVT from GEMM inner loops)
    round_kernel<<<2048,256>>>(x,  xr,  BATCH*SEQ*DIM/4);
    round_kernel<<<32,  256>>>(Q,  qk,             RANK*DIM/4);
    round_kernel<<<32,  256>>>(Km, qk + RANK*DIM,  RANK*DIM/4);
    round_kernel<<<256, 256>>>(VO, vor, DIM*DIM/4);

    // 2) Projections: xqk[16384,64] = x[16384,1024] @ [Q;K]^T  (NT)
    gemm_tf32<128,64,16,true,true><<<dim3(1,128,1),256>>>(
        xr, qk, xqk, DIM, DIM, DIM, 64, 0, 0, 0, 1.0f);

    // 3) Scores per batch: S[4096,4096] = xq @ xk^T / 32  (NT, K=32)
    gemm_tf32<128,128,16,true,false><<<dim3(SEQ/128, SEQ/128, BATCH),256>>>(
        xqk, xqk + RANK, attn, RANK, 64, 64, SEQ,
        (size_t)SEQ*64, (size_t)SEQ*64, (size_t)SEQ*SEQ, 1.0f/32.0f);

    // 4) Row softmax in place (writes tf32-rounded attn)
    softmax_rows<<<BATCH*SEQ, 256>>>(attn);

    // 5) ctx per batch: [4096,1024] = attn[4096,4096] @ x[4096,1024]  (NN)
    gemm_tf32<128,128,16,false,true><<<dim3(DIM/128, SEQ/128, BATCH),256>>>(
        attn, xr, ctx, SEQ, SEQ, DIM, DIM,
        (size_t)SEQ*SEQ, (size_t)SEQ*DIM, (size_t)SEQ*DIM, 1.0f);

    // 6) out: [16384,1024] = ctx @ VO  (NN)
    gemm_tf32<128,128,16,false,false><<<dim3(DIM/128, BATCH*SEQ/128, 1),256>>>(
        ctx, vor, out, DIM, DIM, DIM, DIM, 0, 0, 0, 1.0f);
}

// round 6
// speedup vs baseline: 1.6947x; 1.6947x over previous
#include <cuda_runtime.h>
#include <cuda_fp16.h>
#include <cstdint>
#include <cstddef>

static constexpr int BATCH = 4;
static constexpr int SEQ   = 4096;
static constexpr int DIM   = 1024;
static constexpr int RANK  = 32;

// Scratch (device globals: allocation-free per harness rules)
__device__ float  g_xr  [(size_t)BATCH*SEQ*DIM];   // tf32-rounded x      (64 MB)
__device__ float  g_qk  [64*DIM];                  // concat [Q;K] rounded
__device__ float  g_vor [DIM*DIM];                 // rounded VO
__device__ float  g_xqk [(size_t)BATCH*SEQ*64];    // [b][t][0:32]=xq [32:64]=xk
__device__ __half g_wh  [(size_t)BATCH*SEQ*DIM];   // w = x@VO in fp16    (32 MB)
__device__ __half g_E   [(size_t)BATCH*SEQ*SEQ];   // exp(scores), fp16   (134 MB)
__device__ float  g_part[(size_t)BATCH*SEQ*(SEQ/128)]; // rowsum partials
__device__ float  g_invs[BATCH*SEQ];               // 1 / rowsum

__device__ __forceinline__ float tf32r(float x){
    uint32_t u; asm("cvt.rna.tf32.f32 %0, %1;" : "=r"(u) : "f"(x));
    return __uint_as_float(u);
}

__global__ void __launch_bounds__(256) round_kernel(const float* __restrict__ in,
                                                    float* __restrict__ out, int n4){
    int i = blockIdx.x*blockDim.x + threadIdx.x;
    int stride = gridDim.x*blockDim.x;
    for (; i < n4; i += stride){
        float4 v = ((const float4*)in)[i];
        v.x = tf32r(v.x); v.y = tf32r(v.y); v.z = tf32r(v.z); v.w = tf32r(v.w);
        ((float4*)out)[i] = v;
    }
}

__device__ __forceinline__ void mma_tf32(float* c, const uint32_t* a, const uint32_t* b){
    asm volatile(
        "mma.sync.aligned.m16n8k8.row.col.f32.tf32.tf32.f32 "
        "{%0,%1,%2,%3}, {%4,%5,%6,%7}, {%8,%9}, {%0,%1,%2,%3};\n"
        : "+f"(c[0]), "+f"(c[1]), "+f"(c[2]), "+f"(c[3])
        : "r"(a[0]), "r"(a[1]), "r"(a[2]), "r"(a[3]), "r"(b[0]), "r"(b[1]));
}

__device__ __forceinline__ void mma_f16(float* c, const uint32_t* a, const uint32_t* b){
    asm volatile(
        "mma.sync.aligned.m16n8k16.row.col.f32.f16.f16.f32 "
        "{%0,%1,%2,%3}, {%4,%5,%6,%7}, {%8,%9}, {%0,%1,%2,%3};\n"
        : "+f"(c[0]), "+f"(c[1]), "+f"(c[2]), "+f"(c[3])
        : "r"(a[0]), "r"(a[1]), "r"(a[2]), "r"(a[3]), "r"(b[0]), "r"(b[1]));
}

__device__ __forceinline__ void ldsm4(uint32_t* r, uint32_t a){
    asm volatile("ldmatrix.sync.aligned.m8n8.x4.shared.b16 {%0,%1,%2,%3}, [%4];\n"
        : "=r"(r[0]), "=r"(r[1]), "=r"(r[2]), "=r"(r[3]) : "r"(a));
}
__device__ __forceinline__ void ldsm4t(uint32_t* r, uint32_t a){
    asm volatile("ldmatrix.sync.aligned.m8n8.x4.trans.shared.b16 {%0,%1,%2,%3}, [%4];\n"
        : "=r"(r[0]), "=r"(r[1]), "=r"(r[2]), "=r"(r[3]) : "r"(a));
}

__device__ __forceinline__ void cp16(uint32_t s, const void* g){
    asm volatile("cp.async.ca.shared.global [%0], [%1], 16;\n" :: "r"(s), "l"(g));
}

// ---------------------------------------------------------------------------
// TF32 GEMM (unchanged core). HOUT=true writes __half output.
// ---------------------------------------------------------------------------
template<int BM, int BN, int BK, bool BT, bool ROUND, bool HOUT>
__global__ void __launch_bounds__(256,1)
gemm_tf32(const float* __restrict__ Agp, const float* __restrict__ Bgp,
          void* __restrict__ Cgp, int K, int lda, int ldb, int ldc,
          size_t strA, size_t strB, size_t strC, float alpha)
{
    constexpr int PA  = BK + 4;
    constexpr int PB  = BN + 4;
    constexpr int WM  = BM/2, WN = BN/4;
    constexpr int MF  = WM/16, NF = WN/8;
    constexpr int ASZ = BM*PA;
    constexpr int BSZ = BT ? BN*PA : BK*PB;

    __shared__ float sA[2*ASZ];
    __shared__ float sB[2*BSZ];

    const float* Ag = Agp + blockIdx.z*strA + (size_t)blockIdx.y*BM*lda;
    const float* Bg = Bgp + blockIdx.z*strB +
                      (BT ? (size_t)blockIdx.x*BN*ldb : (size_t)blockIdx.x*BN);

    const int tid  = threadIdx.x;
    const int warp = tid >> 5, lane = tid & 31;
    const int wm   = warp >> 2, wn = warp & 3;
    const int grp  = lane >> 2, tig = lane & 3;

    const uint32_t sAb = (uint32_t)__cvta_generic_to_shared(sA);
    const uint32_t sBb = (uint32_t)__cvta_generic_to_shared(sB);

    float acc[MF][NF][4];
    #pragma unroll
    for (int i=0;i<MF;i++)
        #pragma unroll
        for (int j=0;j<NF;j++)
            #pragma unroll
            for (int q=0;q<4;q++) acc[i][j][q] = 0.f;

    const int KT = K / BK;

    constexpr int AFR   = BK/4;
    constexpr int ARP   = 256/AFR;
    constexpr int APASS = BM/ARP;
    const int a_r = tid / AFR;
    const int a_c = (tid % AFR) * 4;
    constexpr int BTPASS = (BN/ARP > 0) ? BN/ARP : 1;
    constexpr int NFR   = BN/4;
    constexpr int NRP   = 256/NFR;
    constexpr int NPASS = BK/NRP;
    const int b_r = tid / NFR;
    const int b_c = (tid % NFR) * 4;

    auto load_tile = [&](int kt, int buf){
        const float* Ak = Ag + kt*BK;
        #pragma unroll
        for (int p=0;p<APASS;p++){
            int r = a_r + p*ARP;
            cp16(sAb + (uint32_t)(buf*ASZ + r*PA + a_c)*4u, Ak + (size_t)r*lda + a_c);
        }
        if constexpr (BT) {
            const float* Bk = Bg + kt*BK;
            #pragma unroll
            for (int p=0;p<BTPASS;p++){
                int r = a_r + p*ARP;
                cp16(sBb + (uint32_t)(buf*BSZ + r*PA + a_c)*4u, Bk + (size_t)r*ldb + a_c);
            }
        } else {
            const float* Bk = Bg + (size_t)kt*BK*ldb;
            #pragma unroll
            for (int p=0;p<NPASS;p++){
                int r = b_r + p*NRP;
                cp16(sBb + (uint32_t)(buf*BSZ + r*PB + b_c)*4u, Bk + (size_t)r*ldb + b_c);
            }
        }
    };

    auto compute = [&](int buf){
        const float* cA = sA + buf*ASZ;
        const float* cB = sB + buf*BSZ;
        #pragma unroll
        for (int k8=0; k8<BK/8; k8++){
            uint32_t af[MF][4], bf[NF][2];
            #pragma unroll
            for (int mf=0; mf<MF; mf++){
                int r = wm*WM + mf*16 + grp;
                const float* base = cA + r*PA + k8*8 + tig;
                af[mf][0] = __float_as_uint(base[0]);
                af[mf][1] = __float_as_uint(base[8*PA]);
                af[mf][2] = __float_as_uint(base[4]);
                af[mf][3] = __float_as_uint(base[8*PA+4]);
            }
            #pragma unroll
            for (int nf=0; nf<NF; nf++){
                int n = wn*WN + nf*8 + grp;
                if constexpr (BT) {
                    const float* base = cB + n*PA + k8*8 + tig;
                    bf[nf][0] = __float_as_uint(base[0]);
                    bf[nf][1] = __float_as_uint(base[4]);
                } else {
                    const float* base = cB + (k8*8+tig)*PB + n;
                    bf[nf][0] = __float_as_uint(base[0]);
                    bf[nf][1] = __float_as_uint(base[4*PB]);
                }
            }
            #pragma unroll
            for (int mf=0; mf<MF; mf++)
                #pragma unroll
                for (int nf=0; nf<NF; nf++)
                    mma_tf32(acc[mf][nf], af[mf], bf[nf]);
        }
    };

    load_tile(0, 0);
    asm volatile("cp.async.commit_group;\n");
    for (int kt=0; kt<KT; kt++){
        if (kt+1 < KT){
            load_tile(kt+1, (kt+1)&1);
            asm volatile("cp.async.commit_group;\n");
            asm volatile("cp.async.wait_group 1;\n");
        } else {
            asm volatile("cp.async.wait_group 0;\n");
        }
        __syncthreads();
        compute(kt&1);
        __syncthreads();
    }

    if constexpr (HOUT){
        __half* Cg = (__half*)Cgp + blockIdx.z*strC +
                     (size_t)blockIdx.y*BM*ldc + (size_t)blockIdx.x*BN;
        #pragma unroll
        for (int mf=0; mf<MF; mf++){
            int r = wm*WM + mf*16 + grp;
            #pragma unroll
            for (int nf=0; nf<NF; nf++){
                int c = wn*WN + nf*8 + tig*2;
                *(__half2*)(Cg + (size_t)r*ldc + c) =
                    __floats2half2_rn(alpha*acc[mf][nf][0], alpha*acc[mf][nf][1]);
                *(__half2*)(Cg + (size_t)(r+8)*ldc + c) =
                    __floats2half2_rn(alpha*acc[mf][nf][2], alpha*acc[mf][nf][3]);
            }
        }
    } else {
        float* Cg = (float*)Cgp + blockIdx.z*strC +
                    (size_t)blockIdx.y*BM*ldc + (size_t)blockIdx.x*BN;
        #pragma unroll
        for (int mf=0; mf<MF; mf++){
            int r = wm*WM + mf*16 + grp;
            #pragma unroll
            for (int nf=0; nf<NF; nf++){
                int c = wn*WN + nf*8 + tig*2;
                float2 v0, v1;
                v0.x = alpha*acc[mf][nf][0]; v0.y = alpha*acc[mf][nf][1];
                v1.x = alpha*acc[mf][nf][2]; v1.y = alpha*acc[mf][nf][3];
                if (ROUND){
                    v0.x = tf32r(v0.x); v0.y = tf32r(v0.y);
                    v1.x = tf32r(v1.x); v1.y = tf32r(v1.y);
                }
                *(float2*)(Cg + (size_t)r*ldc + c)     = v0;
                *(float2*)(Cg + (size_t)(r+8)*ldc + c) = v1;
            }
        }
    }
}

// ---------------------------------------------------------------------------
// E = exp(scores) (fp16, unnormalized) + per-tile rowsum partials.
// grid (nt=SEQ/128, qt=SEQ/128, b), 256 threads.
// ---------------------------------------------------------------------------
__global__ void __launch_bounds__(256,1)
scores_exp(const float* __restrict__ xqk, __half* __restrict__ E,
           float* __restrict__ part)
{
    constexpr int PA = 36;
    __shared__ float sQ[128*PA];
    __shared__ float sK[128*PA];
    __shared__ float spart[4][128];

    const int b = blockIdx.z, qt = blockIdx.y, nt = blockIdx.x;
    const int tid = threadIdx.x, warp = tid>>5, lane = tid&31;
    const int wm = warp>>2, wn = warp&3, grp = lane>>2, tig = lane&3;

    const uint32_t sQb = (uint32_t)__cvta_generic_to_shared(sQ);
    const uint32_t sKb = (uint32_t)__cvta_generic_to_shared(sK);

    // xq rows at +0, xk rows at +32 within each 64-float xqk row
    const int lr = tid>>3, lc = (tid&7)*4;
    const float* Qg = xqk + ((size_t)b*SEQ + qt*128)*64;
    const float* Kg = xqk + ((size_t)b*SEQ + nt*128)*64 + 32;
    #pragma unroll
    for (int p=0;p<4;p++){
        int r = lr + p*32;
        cp16(sQb + (uint32_t)(r*PA + lc)*4u, Qg + (size_t)r*64 + lc);
        cp16(sKb + (uint32_t)(r*PA + lc)*4u, Kg + (size_t)r*64 + lc);
    }
    asm volatile("cp.async.commit_group;\n");
    asm volatile("cp.async.wait_group 0;\n");
    __syncthreads();

    float acc[4][4][4];
    #pragma unroll
    for (int i=0;i<4;i++)
        #pragma unroll
        for (int j=0;j<4;j++)
            #pragma unroll
            for (int q=0;q<4;q++) acc[i][j][q]=0.f;

    #pragma unroll
    for (int k8=0;k8<4;k8++){
        uint32_t af[4][4], bf[4][2];
        #pragma unroll
        for (int mf=0;mf<4;mf++){
            int r = wm*64 + mf*16 + grp;
            const float* base = sQ + r*PA + k8*8 + tig;
            af[mf][0]=__float_as_uint(base[0]);
            af[mf][1]=__float_as_uint(base[8*PA]);
            af[mf][2]=__float_as_uint(base[4]);
            af[mf][3]=__float_as_uint(base[8*PA+4]);
        }
        #pragma unroll
        for (int nf=0;nf<4;nf++){
            int n = wn*32 + nf*8 + grp;
            const float* base = sK + n*PA + k8*8 + tig;
            bf[nf][0]=__float_as_uint(base[0]);
            bf[nf][1]=__float_as_uint(base[4]);
        }
        #pragma unroll
        for (int mf=0;mf<4;mf++)
            #pragma unroll
            for (int nf=0;nf<4;nf++)
                mma_tf32(acc[mf][nf], af[mf], bf[nf]);
    }

    // epilogue: exp, store fp16, accumulate rowsums (of the rounded values)
    const float isc = 1.0f/32.0f;
    float rs[4][2];
    #pragma unroll
    for (int mf=0;mf<4;mf++){ rs[mf][0]=0.f; rs[mf][1]=0.f; }

    #pragma unroll
    for (int mf=0;mf<4;mf++){
        int r = wm*64 + mf*16 + grp;
        size_t rowo = ((size_t)b*SEQ + qt*128 + r)*SEQ + nt*128;
        #pragma unroll
        for (int nf=0;nf<4;nf++){
            int c = wn*32 + nf*8 + tig*2;
            float e0 = __expf(acc[mf][nf][0]*isc);
            float e1 = __expf(acc[mf][nf][1]*isc);
            float e2 = __expf(acc[mf][nf][2]*isc);
            float e3 = __expf(acc[mf][nf][3]*isc);
            __half2 h0 = __floats2half2_rn(e0,e1);
            __half2 h1 = __floats2half2_rn(e2,e3);
            *(__half2*)&E[rowo + c]         = h0;
            *(__half2*)&E[rowo + 8*SEQ + c] = h1;
            float2 f0 = __half22float2(h0);
            float2 f1 = __half22float2(h1);
            rs[mf][0] += f0.x + f0.y;
            rs[mf][1] += f1.x + f1.y;
        }
    }
    #pragma unroll
    for (int mf=0;mf<4;mf++){
        #pragma unroll
        for (int j=0;j<2;j++){
            float v = rs[mf][j];
            v += __shfl_xor_sync(0xffffffffu, v, 1);
            v += __shfl_xor_sync(0xffffffffu, v, 2);
            if (tig==0) spart[wn][wm*64 + mf*16 + grp + j*8] = v;
        }
    }
    __syncthreads();
    if (tid < 128){
        float s = spart[0][tid] + spart[1][tid] + spart[2][tid] + spart[3][tid];
        part[((size_t)b*SEQ + qt*128 + tid)*(SEQ/128) + nt] = s;
    }
}

__global__ void __launch_bounds__(256) invs_kernel(const float* __restrict__ part,
                                                   float* __restrict__ invs){
    int r = blockIdx.x*blockDim.x + threadIdx.x;
    const float* p = part + (size_t)r*(SEQ/128);
    float s = 0.f;
    #pragma unroll
    for (int i=0;i<SEQ/128;i++) s += p[i];
    invs[r] = 1.0f/s;
}

// ---------------------------------------------------------------------------
// out[b,t,:] = invs[b,t] * (E[b,t,:] @ w[b,:,:])   — fp16 mma, fp32 accum.
// grid (DIM/128, SEQ/128, BATCH) — e-chunk fastest for L2 reuse of E slices.
// ---------------------------------------------------------------------------
__global__ void __launch_bounds__(256,1)
egemm(const __half* __restrict__ E, const __half* __restrict__ W,
      const float* __restrict__ invs, float* __restrict__ out)
{
    constexpr int BK = 32, PA = 56, PB = 136;   // strides in halfs (16B-aligned, CF)
    __shared__ __half sA[2][128*PA];
    __shared__ __half sB[2][BK*PB];

    const int b = blockIdx.z, qt = blockIdx.y, ec = blockIdx.x;
    const __half* Ag = E + ((size_t)b*SEQ + qt*128)*SEQ;
    const __half* Bg = W + (size_t)b*SEQ*DIM + ec*128;

    const int tid = threadIdx.x, warp = tid>>5, lane = tid&31;
    const int wm = warp>>2, wn = warp&3, grp = lane>>2, tig = lane&3;

    const uint32_t sAb = (uint32_t)__cvta_generic_to_shared(sA);
    const uint32_t sBb = (uint32_t)__cvta_generic_to_shared(sB);

    float acc[4][4][4];
    #pragma unroll
    for (int i=0;i<4;i++)
        #pragma unroll
        for (int j=0;j<4;j++)
            #pragma unroll
            for (int q=0;q<4;q++) acc[i][j][q]=0.f;

    const int ar = tid>>2,  ac = (tid&3)*8;    // A: 4×16B chunks per 32-half row
    const int br = tid>>4,  bc = (tid&15)*8;   // B: 16×16B chunks per 128-half row

    auto load_tile = [&](int kt, int buf){
        const __half* Ak = Ag + kt*BK;
        #pragma unroll
        for (int p=0;p<2;p++){
            int r = ar + p*64;
            cp16(sAb + (uint32_t)(buf*128*PA + r*PA + ac)*2u, Ak + (size_t)r*SEQ + ac);
        }
        const __half* Bk = Bg + (size_t)kt*BK*DIM;
        #pragma unroll
        for (int p=0;p<2;p++){
            int r = br + p*16;
            cp16(sBb + (uint32_t)(buf*BK*PB + r*PB + bc)*2u, Bk + (size_t)r*DIM + bc);
        }
    };

    auto compute = [&](int buf){
        #pragma unroll
        for (int ks=0; ks<2; ks++){
            uint32_t af[4][4], bf[2][4];
            #pragma unroll
            for (int mf=0; mf<4; mf++){
                int row  = wm*64 + mf*16 + (lane & 15);
                int colh = ks*16 + ((lane>>4)<<3);
                ldsm4(af[mf], sAb + (uint32_t)(buf*128*PA + row*PA + colh)*2u);
            }
            #pragma unroll
            for (int nh=0; nh<2; nh++){
                int row = ks*16 + (lane & 15);
                int col = wn*32 + nh*16 + ((lane>>4)<<3);
                ldsm4t(bf[nh], sBb + (uint32_t)(buf*BK*PB + row*PB + col)*2u);
            }
            #pragma unroll
            for (int mf=0; mf<4; mf++)
                #pragma unroll
                for (int nf=0; nf<4; nf++)
                    mma_f16(acc[mf][nf], af[mf], &bf[nf>>1][(nf&1)*2]);
        }
    };

    load_tile(0, 0);
    asm volatile("cp.async.commit_group;\n");
    const int KT = SEQ/BK;
    for (int kt=0; kt<KT; kt++){
        if (kt+1 < KT){
            load_tile(kt+1, (kt+1)&1);
            asm volatile("cp.async.commit_group;\n");
            asm volatile("cp.async.wait_group 1;\n");
        } else {
            asm volatile("cp.async.wait_group 0;\n");
        }
        __syncthreads();
        compute(kt&1);
        __syncthreads();
    }

    #pragma unroll
    for (int mf=0; mf<4; mf++){
        int r  = wm*64 + mf*16 + grp;
        int t0 = qt*128 + r;
        float s0 = invs[b*SEQ + t0];
        float s1 = invs[b*SEQ + t0 + 8];
        #pragma unroll
        for (int nf=0; nf<4; nf++){
            int c = ec*128 + wn*32 + nf*8 + tig*2;
            float2 v0, v1;
            v0.x = acc[mf][nf][0]*s0; v0.y = acc[mf][nf][1]*s0;
            v1.x = acc[mf][nf][2]*s1; v1.y = acc[mf][nf][3]*s1;
            *(float2*)&out[((size_t)b*SEQ + t0    )*DIM + c] = v0;
            *(float2*)&out[((size_t)b*SEQ + t0 + 8)*DIM + c] = v1;
        }
    }
}

extern "C" void kernel_launch(void* const* d_in, const int* in_sizes, int n_in,
                              void* d_out, int out_size){
    const float* x  = (const float*)d_in[0];
    const float* Q  = (const float*)d_in[1];
    const float* Km = (const float*)d_in[2];
    const float* VO = (const float*)d_in[3];
    float* out = (float*)d_out;

    float *xr, *qk, *vor, *xqk, *part, *invs;
    __half *wh, *E;
    cudaGetSymbolAddress((void**)&xr,   g_xr);
    cudaGetSymbolAddress((void**)&qk,   g_qk);
    cudaGetSymbolAddress((void**)&vor,  g_vor);
    cudaGetSymbolAddress((void**)&xqk,  g_xqk);
    cudaGetSymbolAddress((void**)&wh,   g_wh);
    cudaGetSymbolAddress((void**)&E,    g_E);
    cudaGetSymbolAddress((void**)&part, g_part);
    cudaGetSymbolAddress((void**)&invs, g_invs);

    // 1) TF32 pre-rounding
    round_kernel<<<2048,256>>>(x,  xr,  BATCH*SEQ*DIM/4);
    round_kernel<<<32,  256>>>(Q,  qk,             RANK*DIM/4);
    round_kernel<<<32,  256>>>(Km, qk + RANK*DIM,  RANK*DIM/4);
    round_kernel<<<256, 256>>>(VO, vor, DIM*DIM/4);

    // 2) Projections: xqk[16384,64] = x @ [Q;K]^T  (NT)
    gemm_tf32<128,64,16,true,true,false><<<dim3(1,128,1),256>>>(
        xr, qk, xqk, DIM, DIM, DIM, 64, 0, 0, 0, 1.0f);

    // 3) w = x @ VO  (NN), fp16 output
    gemm_tf32<128,128,16,false,false,true><<<dim3(DIM/128, BATCH*SEQ/128, 1),256>>>(
        xr, vor, wh, DIM, DIM, DIM, DIM, 0, 0, 0, 1.0f);

    // 4) E = exp(xq@xk^T / 32), fp16, unnormalized + rowsum partials
    scores_exp<<<dim3(SEQ/128, SEQ/128, BATCH),256>>>(xqk, E, part);

    // 5) invs = 1 / rowsum
    invs_kernel<<<BATCH*SEQ/256,256>>>(part, invs);

    // 6) out = invs ⊙ (E @ w)   (fp16 mma, fp32 accumulate)
    egemm<<<dim3(DIM/128, SEQ/128, BATCH),256>>>(E, wh, invs, out);
}

// round 11
// speedup vs baseline: 2.4726x; 1.4590x over previous
#include <cuda_runtime.h>
#include <cuda_fp16.h>
#include <cstdint>
#include <cstddef>

static constexpr int BATCH = 4;
static constexpr int SEQ   = 4096;
static constexpr int DIM   = 1024;
static constexpr int RANK  = 32;

// Scratch (device globals: allocation-free per harness rules)
__device__ __align__(256) float  g_xr  [(size_t)BATCH*SEQ*DIM]; // tf32-rounded x (proj)
__device__ __align__(256) __half g_xh  [(size_t)BATCH*SEQ*DIM]; // fp16 x (w-GEMM)
__device__ __align__(256) float  g_qk  [64*DIM];                // [Q;K] tf32-rounded
__device__ __align__(256) __half g_voh [DIM*DIM];               // VO fp16 [d][e]
__device__ __align__(256) float  g_xqk [(size_t)BATCH*SEQ*64];  // xq|xk
__device__ __align__(256) __half g_wh  [(size_t)BATCH*SEQ*DIM]; // w = x@VO fp16
__device__ __align__(256) __half g_E   [(size_t)BATCH*SEQ*SEQ]; // exp(scores) fp16
__device__ __align__(256) float  g_part[(size_t)BATCH*SEQ*(SEQ/128)];
__device__ __align__(256) float  g_invs[BATCH*SEQ];

__device__ __forceinline__ float tf32r(float x){
    uint32_t u; asm("cvt.rna.tf32.f32 %0, %1;" : "=r"(u) : "f"(x));
    return __uint_as_float(u);
}

__global__ void __launch_bounds__(256) round_kernel(const float* __restrict__ in,
                                                    float* __restrict__ out, int n4){
    int i = blockIdx.x*blockDim.x + threadIdx.x;
    int stride = gridDim.x*blockDim.x;
    for (; i < n4; i += stride){
        float4 v = ((const float4*)in)[i];
        v.x = tf32r(v.x); v.y = tf32r(v.y); v.z = tf32r(v.z); v.w = tf32r(v.w);
        ((float4*)out)[i] = v;
    }
}

__global__ void __launch_bounds__(256) round_half(const float* __restrict__ in,
                                                  __half* __restrict__ out, int n4){
    int i = blockIdx.x*blockDim.x + threadIdx.x;
    int stride = gridDim.x*blockDim.x;
    for (; i < n4; i += stride){
        float4 v = ((const float4*)in)[i];
        ((__half2*)out)[2*i]   = __floats2half2_rn(v.x, v.y);
        ((__half2*)out)[2*i+1] = __floats2half2_rn(v.z, v.w);
    }
}

__device__ __forceinline__ void mma_tf32(float* c, const uint32_t* a, const uint32_t* b){
    asm volatile(
        "mma.sync.aligned.m16n8k8.row.col.f32.tf32.tf32.f32 "
        "{%0,%1,%2,%3}, {%4,%5,%6,%7}, {%8,%9}, {%0,%1,%2,%3};\n"
        : "+f"(c[0]), "+f"(c[1]), "+f"(c[2]), "+f"(c[3])
        : "r"(a[0]), "r"(a[1]), "r"(a[2]), "r"(a[3]), "r"(b[0]), "r"(b[1]));
}

__device__ __forceinline__ void mma_f16(float* c, const uint32_t* a, const uint32_t* b){
    asm volatile(
        "mma.sync.aligned.m16n8k16.row.col.f32.f16.f16.f32 "
        "{%0,%1,%2,%3}, {%4,%5,%6,%7}, {%8,%9}, {%0,%1,%2,%3};\n"
        : "+f"(c[0]), "+f"(c[1]), "+f"(c[2]), "+f"(c[3])
        : "r"(a[0]), "r"(a[1]), "r"(a[2]), "r"(a[3]), "r"(b[0]), "r"(b[1]));
}

__device__ __forceinline__ void ldsm4(uint32_t* r, uint32_t a){
    asm volatile("ldmatrix.sync.aligned.m8n8.x4.shared.b16 {%0,%1,%2,%3}, [%4];\n"
        : "=r"(r[0]), "=r"(r[1]), "=r"(r[2]), "=r"(r[3]) : "r"(a));
}
__device__ __forceinline__ void ldsm4t(uint32_t* r, uint32_t a){
    asm volatile("ldmatrix.sync.aligned.m8n8.x4.trans.shared.b16 {%0,%1,%2,%3}, [%4];\n"
        : "=r"(r[0]), "=r"(r[1]), "=r"(r[2]), "=r"(r[3]) : "r"(a));
}

__device__ __forceinline__ void cp16(uint32_t s, const void* g){
    asm volatile("cp.async.ca.shared.global [%0], [%1], 16;\n" :: "r"(s), "l"(g));
}

// ---------------------------------------------------------------------------
// TF32 mma.sync GEMM — retained for the small projection GEMM only. NT form.
// ---------------------------------------------------------------------------
template<int BM, int BN, int BK>
__global__ void __launch_bounds__(256,1)
gemm_tf32_nt(const float* __restrict__ Agp, const float* __restrict__ Bgp,
             float* __restrict__ Cgp, int K, int lda, int ldb, int ldc)
{
    constexpr int PA  = BK + 4;
    constexpr int WM  = BM/2, WN = BN/4;
    constexpr int MF  = WM/16, NF = WN/8;
    constexpr int ASZ = BM*PA;
    constexpr int BSZ = BN*PA;

    __shared__ float sA[2*ASZ];
    __shared__ float sB[2*BSZ];

    const float* Ag = Agp + (size_t)blockIdx.y*BM*lda;
    const float* Bg = Bgp + (size_t)blockIdx.x*BN*ldb;
    float* Cg = Cgp + (size_t)blockIdx.y*BM*ldc + (size_t)blockIdx.x*BN;

    const int tid  = threadIdx.x;
    const int warp = tid >> 5, lane = tid & 31;
    const int wm   = warp >> 2, wn = warp & 3;
    const int grp  = lane >> 2, tig = lane & 3;

    const uint32_t sAb = (uint32_t)__cvta_generic_to_shared(sA);
    const uint32_t sBb = (uint32_t)__cvta_generic_to_shared(sB);

    float acc[MF][NF][4];
    #pragma unroll
    for (int i=0;i<MF;i++)
        #pragma unroll
        for (int j=0;j<NF;j++)
            #pragma unroll
            for (int q=0;q<4;q++) acc[i][j][q] = 0.f;

    const int KT = K / BK;
    constexpr int AFR   = BK/4;
    constexpr int ARP   = 256/AFR;
    constexpr int APASS = BM/ARP;
    constexpr int BPASS = (BN/ARP > 0) ? BN/ARP : 1;
    const int a_r = tid / AFR;
    const int a_c = (tid % AFR) * 4;

    auto load_tile = [&](int kt, int buf){
        const float* Ak = Ag + kt*BK;
        #pragma unroll
        for (int p=0;p<APASS;p++){
            int r = a_r + p*ARP;
            cp16(sAb + (uint32_t)(buf*ASZ + r*PA + a_c)*4u, Ak + (size_t)r*lda + a_c);
        }
        const float* Bk = Bg + kt*BK;
        #pragma unroll
        for (int p=0;p<BPASS;p++){
            int r = a_r + p*ARP;
            cp16(sBb + (uint32_t)(buf*BSZ + r*PA + a_c)*4u, Bk + (size_t)r*ldb + a_c);
        }
    };

    auto compute = [&](int buf){
        const float* cA = sA + buf*ASZ;
        const float* cB = sB + buf*BSZ;
        #pragma unroll
        for (int k8=0; k8<BK/8; k8++){
            uint32_t af[MF][4], bf[NF][2];
            #pragma unroll
            for (int mf=0; mf<MF; mf++){
                int r = wm*WM + mf*16 + grp;
                const float* base = cA + r*PA + k8*8 + tig;
                af[mf][0] = __float_as_uint(base[0]);
                af[mf][1] = __float_as_uint(base[8*PA]);
                af[mf][2] = __float_as_uint(base[4]);
                af[mf][3] = __float_as_uint(base[8*PA+4]);
            }
            #pragma unroll
            for (int nf=0; nf<NF; nf++){
                int n = wn*WN + nf*8 + grp;
                const float* base = cB + n*PA + k8*8 + tig;
                bf[nf][0] = __float_as_uint(base[0]);
                bf[nf][1] = __float_as_uint(base[4]);
            }
            #pragma unroll
            for (int mf=0; mf<MF; mf++)
                #pragma unroll
                for (int nf=0; nf<NF; nf++)
                    mma_tf32(acc[mf][nf], af[mf], bf[nf]);
        }
    };

    load_tile(0, 0);
    asm volatile("cp.async.commit_group;\n");
    for (int kt=0; kt<KT; kt++){
        if (kt+1 < KT){
            load_tile(kt+1, (kt+1)&1);
            asm volatile("cp.async.commit_group;\n");
            asm volatile("cp.async.wait_group 1;\n");
        } else {
            asm volatile("cp.async.wait_group 0;\n");
        }
        __syncthreads();
        compute(kt&1);
        __syncthreads();
    }

    #pragma unroll
    for (int mf=0; mf<MF; mf++){
        int r = wm*WM + mf*16 + grp;
        #pragma unroll
        for (int nf=0; nf<NF; nf++){
            int c = wn*WN + nf*8 + tig*2;
            float2 v0, v1;
            v0.x = tf32r(acc[mf][nf][0]); v0.y = tf32r(acc[mf][nf][1]);
            v1.x = tf32r(acc[mf][nf][2]); v1.y = tf32r(acc[mf][nf][3]);
            *(float2*)(Cg + (size_t)r*ldc + c)     = v0;
            *(float2*)(Cg + (size_t)(r+8)*ldc + c) = v1;
        }
    }
}

// ===========================================================================
// fp16 multistage NN GEMM: C[M,N] = A[M,K] @ B[K,N], f32 accumulate.
// CTA 128x128, BK=64, 4-stage cp.async, ONE __syncthreads per K-iter.
// EPI=0: fp16 C.  EPI=1: f32 C scaled per-row by invs (egemm epilogue).
// ===========================================================================
static constexpr int HG_PA   = 72;    // A row stride (halfs)
static constexpr int HG_PB   = 136;   // B row stride (halfs)
static constexpr int HG_BK   = 64;
static constexpr int HG_STG  = 128*HG_PA + HG_BK*HG_PB;    // 17920 halfs/stage
static constexpr int HG_SMEM = 4*HG_STG*2;                 // 143360 bytes

template<int EPI>
__global__ void __launch_bounds__(256,1)
hgemm(const __half* __restrict__ Agp, const __half* __restrict__ Bgp,
      void* __restrict__ Cgp, const float* __restrict__ invs,
      int K, int lda, int ldb, int ldc,
      size_t strA, size_t strB, size_t strC)
{
    extern __shared__ __half sh[];
    const uint32_t shb = (uint32_t)__cvta_generic_to_shared(sh);

    const int b = blockIdx.z, mt = blockIdx.y, nt = blockIdx.x;
    const __half* Ag = Agp + b*strA + (size_t)mt*128*lda;
    const __half* Bg = Bgp + b*strB + (size_t)nt*128;

    const int tid = threadIdx.x, warp = tid>>5, lane = tid&31;
    const int wm = warp>>2, wn = warp&3, grp = lane>>2, tig = lane&3;

    float acc[4][4][4];
    #pragma unroll
    for (int i=0;i<4;i++)
        #pragma unroll
        for (int j=0;j<4;j++)
            #pragma unroll
            for (int q=0;q<4;q++) acc[i][j][q]=0.f;

    auto load_stage = [&](int kt, int s){
        const uint32_t ab = shb + (uint32_t)(s*HG_STG)*2u;
        const uint32_t bb = ab + (uint32_t)(128*HG_PA)*2u;
        #pragma unroll
        for (int p=0;p<4;p++){                        // A: 128 rows x 8 chunks
            int ch = tid + p*256, row = ch>>3, c = ch&7;
            cp16(ab + (uint32_t)(row*HG_PA + c*8)*2u,
                 Ag + (size_t)row*lda + kt*HG_BK + c*8);
        }
        #pragma unroll
        for (int p=0;p<4;p++){                        // B: 64 rows x 16 chunks
            int ch = tid + p*256, row = ch>>4, c = ch&15;
            cp16(bb + (uint32_t)(row*HG_PB + c*8)*2u,
                 Bg + (size_t)(kt*HG_BK + row)*ldb + c*8);
        }
        asm volatile("cp.async.commit_group;\n");
    };

    auto compute = [&](int s){
        const uint32_t ab = shb + (uint32_t)(s*HG_STG)*2u;
        const uint32_t bb = ab + (uint32_t)(128*HG_PA)*2u;
        #pragma unroll
        for (int ks=0; ks<HG_BK/16; ks++){
            uint32_t af[4][4], bf[2][4];
            #pragma unroll
            for (int mf=0; mf<4; mf++){
                int row  = wm*64 + mf*16 + (lane & 15);
                int colh = ks*16 + ((lane>>4)<<3);
                ldsm4(af[mf], ab + (uint32_t)(row*HG_PA + colh)*2u);
            }
            #pragma unroll
            for (int nh=0; nh<2; nh++){
                int row = ks*16 + (lane & 15);
                int col = wn*32 + nh*16 + ((lane>>4)<<3);
                ldsm4t(bf[nh], bb + (uint32_t)(row*HG_PB + col)*2u);
            }
            #pragma unroll
            for (int mf=0; mf<4; mf++)
                #pragma unroll
                for (int nf=0; nf<4; nf++)
                    mma_f16(acc[mf][nf], af[mf], &bf[nf>>1][(nf&1)*2]);
        }
    };

    const int KT = K / HG_BK;
    load_stage(0,0); load_stage(1,1); load_stage(2,2);

    #pragma unroll 1
    for (int kt=0; kt<KT; kt++){
        const int rem = KT-1-kt;
        if      (rem >= 2) asm volatile("cp.async.wait_group 2;\n");
        else if (rem == 1) asm volatile("cp.async.wait_group 1;\n");
        else               asm volatile("cp.async.wait_group 0;\n");
        __syncthreads();                 // stage kt resident; stage (kt+3)&3 free
        if (kt+3 < KT) load_stage(kt+3, (kt+3)&3);
        compute(kt&3);
    }

    if constexpr (EPI == 0){
        __half* Cg = (__half*)Cgp + b*strC + (size_t)mt*128*ldc + (size_t)nt*128;
        #pragma unroll
        for (int mf=0; mf<4; mf++){
            int r = wm*64 + mf*16 + grp;
            #pragma unroll
            for (int nf=0; nf<4; nf++){
                int c = wn*32 + nf*8 + tig*2;
                *(__half2*)(Cg + (size_t)r*ldc + c) =
                    __floats2half2_rn(acc[mf][nf][0], acc[mf][nf][1]);
                *(__half2*)(Cg + (size_t)(r+8)*ldc + c) =
                    __floats2half2_rn(acc[mf][nf][2], acc[mf][nf][3]);
            }
        }
    } else {
        float* Cg = (float*)Cgp + b*strC + (size_t)mt*128*ldc + (size_t)nt*128;
        const float* ivp = invs + b*SEQ + mt*128;
        #pragma unroll
        for (int mf=0; mf<4; mf++){
            int r = wm*64 + mf*16 + grp;
            float s0 = ivp[r], s1 = ivp[r+8];
            #pragma unroll
            for (int nf=0; nf<4; nf++){
                int c = wn*32 + nf*8 + tig*2;
                float2 v0, v1;
                v0.x = acc[mf][nf][0]*s0; v0.y = acc[mf][nf][1]*s0;
                v1.x = acc[mf][nf][2]*s1; v1.y = acc[mf][nf][3]*s1;
                *(float2*)(Cg + (size_t)r*ldc + c)     = v0;
                *(float2*)(Cg + (size_t)(r+8)*ldc + c) = v1;
            }
        }
    }
}

// ---------------------------------------------------------------------------
// E = exp(scores) (fp16, unnormalized) + per-tile rowsum partials.
// ---------------------------------------------------------------------------
__global__ void __launch_bounds__(256,1)
scores_exp(const float* __restrict__ xqk, __half* __restrict__ E,
           float* __restrict__ part)
{
    constexpr int PA = 36;
    __shared__ float sQ[128*PA];
    __shared__ float sK[128*PA];
    __shared__ float spart[4][128];

    const int b = blockIdx.z, qt = blockIdx.y, nt = blockIdx.x;
    const int tid = threadIdx.x, warp = tid>>5, lane = tid&31;
    const int wm = warp>>2, wn = warp&3, grp = lane>>2, tig = lane&3;

    const uint32_t sQb = (uint32_t)__cvta_generic_to_shared(sQ);
    const uint32_t sKb = (uint32_t)__cvta_generic_to_shared(sK);

    const int lr = tid>>3, lc = (tid&7)*4;
    const float* Qg = xqk + ((size_t)b*SEQ + qt*128)*64;
    const float* Kg = xqk + ((size_t)b*SEQ + nt*128)*64 + 32;
    #pragma unroll
    for (int p=0;p<4;p++){
        int r = lr + p*32;
        cp16(sQb + (uint32_t)(r*PA + lc)*4u, Qg + (size_t)r*64 + lc);
        cp16(sKb + (uint32_t)(r*PA + lc)*4u, Kg + (size_t)r*64 + lc);
    }
    asm volatile("cp.async.commit_group;\n");
    asm volatile("cp.async.wait_group 0;\n");
    __syncthreads();

    float acc[4][4][4];
    #pragma unroll
    for (int i=0;i<4;i++)
        #pragma unroll
        for (int j=0;j<4;j++)
            #pragma unroll
            for (int q=0;q<4;q++) acc[i][j][q]=0.f;

    #pragma unroll
    for (int k8=0;k8<4;k8++){
        uint32_t af[4][4], bf[4][2];
        #pragma unroll
        for (int mf=0;mf<4;mf++){
            int r = wm*64 + mf*16 + grp;
            const float* base = sQ + r*PA + k8*8 + tig;
            af[mf][0]=__float_as_uint(base[0]);
            af[mf][1]=__float_as_uint(base[8*PA]);
            af[mf][2]=__float_as_uint(base[4]);
            af[mf][3]=__float_as_uint(base[8*PA+4]);
        }
        #pragma unroll
        for (int nf=0;nf<4;nf++){
            int n = wn*32 + nf*8 + grp;
            const float* base = sK + n*PA + k8*8 + tig;
            bf[nf][0]=__float_as_uint(base[0]);
            bf[nf][1]=__float_as_uint(base[4]);
        }
        #pragma unroll
        for (int mf=0;mf<4;mf++)
            #pragma unroll
            for (int nf=0;nf<4;nf++)
                mma_tf32(acc[mf][nf], af[mf], bf[nf]);
    }

    const float isc = 1.0f/32.0f;
    float rs[4][2];
    #pragma unroll
    for (int mf=0;mf<4;mf++){ rs[mf][0]=0.f; rs[mf][1]=0.f; }

    #pragma unroll
    for (int mf=0;mf<4;mf++){
        int r = wm*64 + mf*16 + grp;
        size_t rowo = ((size_t)b*SEQ + qt*128 + r)*SEQ + nt*128;
        #pragma unroll
        for (int nf=0;nf<4;nf++){
            int c = wn*32 + nf*8 + tig*2;
            float e0 = __expf(acc[mf][nf][0]*isc);
            float e1 = __expf(acc[mf][nf][1]*isc);
            float e2 = __expf(acc[mf][nf][2]*isc);
            float e3 = __expf(acc[mf][nf][3]*isc);
            __half2 h0 = __floats2half2_rn(e0,e1);
            __half2 h1 = __floats2half2_rn(e2,e3);
            *(__half2*)&E[rowo + c]         = h0;
            *(__half2*)&E[rowo + 8*SEQ + c] = h1;
            float2 f0 = __half22float2(h0);
            float2 f1 = __half22float2(h1);
            rs[mf][0] += f0.x + f0.y;
            rs[mf][1] += f1.x + f1.y;
        }
    }
    #pragma unroll
    for (int mf=0;mf<4;mf++){
        #pragma unroll
        for (int j=0;j<2;j++){
            float v = rs[mf][j];
            v += __shfl_xor_sync(0xffffffffu, v, 1);
            v += __shfl_xor_sync(0xffffffffu, v, 2);
            if (tig==0) spart[wn][wm*64 + mf*16 + grp + j*8] = v;
        }
    }
    __syncthreads();
    if (tid < 128){
        float s = spart[0][tid] + spart[1][tid] + spart[2][tid] + spart[3][tid];
        part[((size_t)b*SEQ + qt*128 + tid)*(SEQ/128) + nt] = s;
    }
}

__global__ void __launch_bounds__(256) invs_kernel(const float* __restrict__ part,
                                                   float* __restrict__ invs){
    int r = blockIdx.x*blockDim.x + threadIdx.x;
    const float* p = part + (size_t)r*(SEQ/128);
    float s = 0.f;
    #pragma unroll
    for (int i=0;i<SEQ/128;i++) s += p[i];
    invs[r] = 1.0f/s;
}

extern "C" void kernel_launch(void* const* d_in, const int* in_sizes, int n_in,
                              void* d_out, int out_size){
    const float* x  = (const float*)d_in[0];
    const float* Q  = (const float*)d_in[1];
    const float* Km = (const float*)d_in[2];
    const float* VO = (const float*)d_in[3];
    float* out = (float*)d_out;

    float *xr, *qk, *xqk, *part, *invs;
    __half *xh, *voh, *wh, *E;
    cudaGetSymbolAddress((void**)&xr,   g_xr);
    cudaGetSymbolAddress((void**)&xh,   g_xh);
    cudaGetSymbolAddress((void**)&qk,   g_qk);
    cudaGetSymbolAddress((void**)&voh,  g_voh);
    cudaGetSymbolAddress((void**)&xqk,  g_xqk);
    cudaGetSymbolAddress((void**)&wh,   g_wh);
    cudaGetSymbolAddress((void**)&E,    g_E);
    cudaGetSymbolAddress((void**)&part, g_part);
    cudaGetSymbolAddress((void**)&invs, g_invs);

    static int cfg_done = 0;
    if (!cfg_done){
        cudaFuncSetAttribute(hgemm<0>, cudaFuncAttributeMaxDynamicSharedMemorySize, HG_SMEM);
        cudaFuncSetAttribute(hgemm<1>, cudaFuncAttributeMaxDynamicSharedMemorySize, HG_SMEM);
        cfg_done = 1;
    }

    // 1) Rounding passes: tf32 x (proj path), fp16 x + fp16 VO (w path)
    round_kernel<<<2048,256>>>(x,  xr,  BATCH*SEQ*DIM/4);
    round_half  <<<2048,256>>>(x,  xh,  BATCH*SEQ*DIM/4);
    round_kernel<<<32,  256>>>(Q,  qk,             RANK*DIM/4);
    round_kernel<<<32,  256>>>(Km, qk + RANK*DIM,  RANK*DIM/4);
    round_half  <<<512, 256>>>(VO, voh, DIM*DIM/4);

    // 2) Projections: xqk[16384,64] = x @ [Q;K]^T  (tf32 NT)
    gemm_tf32_nt<128,64,16><<<dim3(1,128,1),256>>>(xr, qk, xqk, DIM, DIM, DIM, 64);

    // 3) w[b,u,e] = x[b,u,:] @ VO   (fp16 multistage NN, fp16 out)
    hgemm<0><<<dim3(DIM/128, SEQ/128, BATCH), 256, HG_SMEM>>>(
        xh, voh, wh, nullptr, DIM, DIM, DIM, DIM,
        (size_t)SEQ*DIM, 0, (size_t)SEQ*DIM);

    // 4) E = exp(xq@xk^T / 32), fp16, unnormalized + rowsum partials
    scores_exp<<<dim3(SEQ/128, SEQ/128, BATCH),256>>>(xqk, E, part);

    // 5) invs = 1 / rowsum
    invs_kernel<<<BATCH*SEQ/256,256>>>(part, invs);

    // 6) out = invs ⊙ (E @ w)  (fp16 multistage NN, f32 out with row scaling)
    hgemm<1><<<dim3(DIM/128, SEQ/128, BATCH), 256, HG_SMEM>>>(
        E, wh, out, invs, SEQ, SEQ, DIM, DIM,
        (size_t)SEQ*SEQ, (size_t)SEQ*DIM, (size_t)SEQ*DIM);
}

// round 17
// speedup vs baseline: 2.6124x; 1.0565x over previous
#include <cuda_runtime.h>
#include <cuda_fp16.h>
#include <cstdint>
#include <cstddef>

static constexpr int BATCH = 4;
static constexpr int SEQ   = 4096;
static constexpr int DIM   = 1024;
static constexpr int RANK  = 32;

// Scratch (device globals: allocation-free per harness rules)
__device__ __align__(256) float  g_xr  [(size_t)BATCH*SEQ*DIM]; // tf32-rounded x (proj)
__device__ __align__(256) __half g_xh  [(size_t)BATCH*SEQ*DIM]; // fp16 x (w-GEMM)
__device__ __align__(256) float  g_qk  [64*DIM];                // [Q;K] tf32-rounded
__device__ __align__(256) __half g_voh [DIM*DIM];               // VO fp16 [d][e]
__device__ __align__(256) float  g_xqk [(size_t)BATCH*SEQ*64];  // xq|xk
__device__ __align__(256) __half g_wh  [(size_t)BATCH*SEQ*DIM]; // w = x@VO fp16
__device__ __align__(256) __half g_E   [(size_t)BATCH*SEQ*SEQ]; // exp(scores) fp16
__device__ __align__(256) float  g_part[(size_t)BATCH*SEQ*(SEQ/128)];
__device__ __align__(256) float  g_invs[BATCH*SEQ];

__device__ __forceinline__ float tf32r(float x){
    uint32_t u; asm("cvt.rna.tf32.f32 %0, %1;" : "=r"(u) : "f"(x));
    return __uint_as_float(u);
}

// One pass over x: write tf32-rounded f32 AND fp16 copies.
__global__ void __launch_bounds__(256) round_both(const float* __restrict__ in,
                                                  float* __restrict__ outf,
                                                  __half* __restrict__ outh, int n4){
    int i = blockIdx.x*blockDim.x + threadIdx.x;
    int stride = gridDim.x*blockDim.x;
    for (; i < n4; i += stride){
        float4 v = ((const float4*)in)[i];
        ((__half2*)outh)[2*i]   = __floats2half2_rn(v.x, v.y);
        ((__half2*)outh)[2*i+1] = __floats2half2_rn(v.z, v.w);
        v.x = tf32r(v.x); v.y = tf32r(v.y); v.z = tf32r(v.z); v.w = tf32r(v.w);
        ((float4*)outf)[i] = v;
    }
}

__global__ void __launch_bounds__(256) round_kernel(const float* __restrict__ in,
                                                    float* __restrict__ out, int n4){
    int i = blockIdx.x*blockDim.x + threadIdx.x;
    int stride = gridDim.x*blockDim.x;
    for (; i < n4; i += stride){
        float4 v = ((const float4*)in)[i];
        v.x = tf32r(v.x); v.y = tf32r(v.y); v.z = tf32r(v.z); v.w = tf32r(v.w);
        ((float4*)out)[i] = v;
    }
}

__global__ void __launch_bounds__(256) round_half(const float* __restrict__ in,
                                                  __half* __restrict__ out, int n4){
    int i = blockIdx.x*blockDim.x + threadIdx.x;
    int stride = gridDim.x*blockDim.x;
    for (; i < n4; i += stride){
        float4 v = ((const float4*)in)[i];
        ((__half2*)out)[2*i]   = __floats2half2_rn(v.x, v.y);
        ((__half2*)out)[2*i+1] = __floats2half2_rn(v.z, v.w);
    }
}

__device__ __forceinline__ void mma_tf32(float* c, const uint32_t* a, const uint32_t* b){
    asm volatile(
        "mma.sync.aligned.m16n8k8.row.col.f32.tf32.tf32.f32 "
        "{%0,%1,%2,%3}, {%4,%5,%6,%7}, {%8,%9}, {%0,%1,%2,%3};\n"
        : "+f"(c[0]), "+f"(c[1]), "+f"(c[2]), "+f"(c[3])
        : "r"(a[0]), "r"(a[1]), "r"(a[2]), "r"(a[3]), "r"(b[0]), "r"(b[1]));
}

__device__ __forceinline__ void mma_f16(float* c, const uint32_t* a, const uint32_t* b){
    asm volatile(
        "mma.sync.aligned.m16n8k16.row.col.f32.f16.f16.f32 "
        "{%0,%1,%2,%3}, {%4,%5,%6,%7}, {%8,%9}, {%0,%1,%2,%3};\n"
        : "+f"(c[0]), "+f"(c[1]), "+f"(c[2]), "+f"(c[3])
        : "r"(a[0]), "r"(a[1]), "r"(a[2]), "r"(a[3]), "r"(b[0]), "r"(b[1]));
}

__device__ __forceinline__ void ldsm4(uint32_t* r, uint32_t a){
    asm volatile("ldmatrix.sync.aligned.m8n8.x4.shared.b16 {%0,%1,%2,%3}, [%4];\n"
        : "=r"(r[0]), "=r"(r[1]), "=r"(r[2]), "=r"(r[3]) : "r"(a));
}
__device__ __forceinline__ void ldsm4t(uint32_t* r, uint32_t a){
    asm volatile("ldmatrix.sync.aligned.m8n8.x4.trans.shared.b16 {%0,%1,%2,%3}, [%4];\n"
        : "=r"(r[0]), "=r"(r[1]), "=r"(r[2]), "=r"(r[3]) : "r"(a));
}

__device__ __forceinline__ void cp16(uint32_t s, const void* g){
    asm volatile("cp.async.ca.shared.global [%0], [%1], 16;\n" :: "r"(s), "l"(g));
}

// ---------------------------------------------------------------------------
// TF32 mma.sync GEMM — retained for the small projection GEMM only. NT form.
// ---------------------------------------------------------------------------
template<int BM, int BN, int BK>
__global__ void __launch_bounds__(256,1)
gemm_tf32_nt(const float* __restrict__ Agp, const float* __restrict__ Bgp,
             float* __restrict__ Cgp, int K, int lda, int ldb, int ldc)
{
    constexpr int PA  = BK + 4;
    constexpr int WM  = BM/2, WN = BN/4;
    constexpr int MF  = WM/16, NF = WN/8;
    constexpr int ASZ = BM*PA;
    constexpr int BSZ = BN*PA;

    __shared__ float sA[2*ASZ];
    __shared__ float sB[2*BSZ];

    const float* Ag = Agp + (size_t)blockIdx.y*BM*lda;
    const float* Bg = Bgp + (size_t)blockIdx.x*BN*ldb;
    float* Cg = Cgp + (size_t)blockIdx.y*BM*ldc + (size_t)blockIdx.x*BN;

    const int tid  = threadIdx.x;
    const int warp = tid >> 5, lane = tid & 31;
    const int wm   = warp >> 2, wn = warp & 3;
    const int grp  = lane >> 2, tig = lane & 3;

    const uint32_t sAb = (uint32_t)__cvta_generic_to_shared(sA);
    const uint32_t sBb = (uint32_t)__cvta_generic_to_shared(sB);

    float acc[MF][NF][4];
    #pragma unroll
    for (int i=0;i<MF;i++)
        #pragma unroll
        for (int j=0;j<NF;j++)
            #pragma unroll
            for (int q=0;q<4;q++) acc[i][j][q] = 0.f;

    const int KT = K / BK;
    constexpr int AFR   = BK/4;
    constexpr int ARP   = 256/AFR;
    constexpr int APASS = BM/ARP;
    constexpr int BPASS = (BN/ARP > 0) ? BN/ARP : 1;
    const int a_r = tid / AFR;
    const int a_c = (tid % AFR) * 4;

    auto load_tile = [&](int kt, int buf){
        const float* Ak = Ag + kt*BK;
        #pragma unroll
        for (int p=0;p<APASS;p++){
            int r = a_r + p*ARP;
            cp16(sAb + (uint32_t)(buf*ASZ + r*PA + a_c)*4u, Ak + (size_t)r*lda + a_c);
        }
        const float* Bk = Bg + kt*BK;
        #pragma unroll
        for (int p=0;p<BPASS;p++){
            int r = a_r + p*ARP;
            cp16(sBb + (uint32_t)(buf*BSZ + r*PA + a_c)*4u, Bk + (size_t)r*ldb + a_c);
        }
    };

    auto compute = [&](int buf){
        const float* cA = sA + buf*ASZ;
        const float* cB = sB + buf*BSZ;
        #pragma unroll
        for (int k8=0; k8<BK/8; k8++){
            uint32_t af[MF][4], bf[NF][2];
            #pragma unroll
            for (int mf=0; mf<MF; mf++){
                int r = wm*WM + mf*16 + grp;
                const float* base = cA + r*PA + k8*8 + tig;
                af[mf][0] = __float_as_uint(base[0]);
                af[mf][1] = __float_as_uint(base[8*PA]);
                af[mf][2] = __float_as_uint(base[4]);
                af[mf][3] = __float_as_uint(base[8*PA+4]);
            }
            #pragma unroll
            for (int nf=0; nf<NF; nf++){
                int n = wn*WN + nf*8 + grp;
                const float* base = cB + n*PA + k8*8 + tig;
                bf[nf][0] = __float_as_uint(base[0]);
                bf[nf][1] = __float_as_uint(base[4]);
            }
            #pragma unroll
            for (int mf=0; mf<MF; mf++)
                #pragma unroll
                for (int nf=0; nf<NF; nf++)
                    mma_tf32(acc[mf][nf], af[mf], bf[nf]);
        }
    };

    load_tile(0, 0);
    asm volatile("cp.async.commit_group;\n");
    for (int kt=0; kt<KT; kt++){
        if (kt+1 < KT){
            load_tile(kt+1, (kt+1)&1);
            asm volatile("cp.async.commit_group;\n");
            asm volatile("cp.async.wait_group 1;\n");
        } else {
            asm volatile("cp.async.wait_group 0;\n");
        }
        __syncthreads();
        compute(kt&1);
        __syncthreads();
    }

    #pragma unroll
    for (int mf=0; mf<MF; mf++){
        int r = wm*WM + mf*16 + grp;
        #pragma unroll
        for (int nf=0; nf<NF; nf++){
            int c = wn*WN + nf*8 + tig*2;
            float2 v0, v1;
            v0.x = tf32r(acc[mf][nf][0]); v0.y = tf32r(acc[mf][nf][1]);
            v1.x = tf32r(acc[mf][nf][2]); v1.y = tf32r(acc[mf][nf][3]);
            *(float2*)(Cg + (size_t)r*ldc + c)     = v0;
            *(float2*)(Cg + (size_t)(r+8)*ldc + c) = v1;
        }
    }
}

// ===========================================================================
// fp16 multistage NN GEMM: C[M,N] = A[M,K] @ B[K,N], f32 accumulate.
// CTA 128x256, BK=64, 3-stage cp.async, ONE __syncthreads per K-iter.
// EPI=0: fp16 C.  EPI=1: f32 C scaled per-row by invs (egemm epilogue).
// ===========================================================================
static constexpr int HG_BN   = 256;
static constexpr int HG_PA   = 72;    // A row stride (halfs): 36 words ≡ 4 mod 32
static constexpr int HG_PB   = 264;   // B row stride (halfs): 132 words ≡ 4 mod 32
static constexpr int HG_BK   = 64;
static constexpr int HG_STG  = 128*HG_PA + HG_BK*HG_PB;    // 26112 halfs/stage
static constexpr int HG_SMEM = 3*HG_STG*2;                 // 156672 bytes

template<int EPI>
__global__ void __launch_bounds__(256,1)
hgemm(const __half* __restrict__ Agp, const __half* __restrict__ Bgp,
      void* __restrict__ Cgp, const float* __restrict__ invs,
      int K, int lda, int ldb, int ldc,
      size_t strA, size_t strB, size_t strC)
{
    extern __shared__ __half sh[];
    const uint32_t shb = (uint32_t)__cvta_generic_to_shared(sh);

    const int b = blockIdx.z, mt = blockIdx.y, nt = blockIdx.x;
    const __half* Ag = Agp + b*strA + (size_t)mt*128*lda;
    const __half* Bg = Bgp + b*strB + (size_t)nt*HG_BN;

    const int tid = threadIdx.x, warp = tid>>5, lane = tid&31;
    const int wm = warp>>2, wn = warp&3, grp = lane>>2, tig = lane&3;

    float acc[4][8][4];
    #pragma unroll
    for (int i=0;i<4;i++)
        #pragma unroll
        for (int j=0;j<8;j++)
            #pragma unroll
            for (int q=0;q<4;q++) acc[i][j][q]=0.f;

    auto load_stage = [&](int kt, int s){
        const uint32_t ab = shb + (uint32_t)(s*HG_STG)*2u;
        const uint32_t bb = ab + (uint32_t)(128*HG_PA)*2u;
        #pragma unroll
        for (int p=0;p<4;p++){                        // A: 128 rows x 8 chunks
            int ch = tid + p*256, row = ch>>3, c = ch&7;
            cp16(ab + (uint32_t)(row*HG_PA + c*8)*2u,
                 Ag + (size_t)row*lda + kt*HG_BK + c*8);
        }
        #pragma unroll
        for (int p=0;p<8;p++){                        // B: 64 rows x 32 chunks
            int ch = tid + p*256, row = ch>>5, c = ch&31;
            cp16(bb + (uint32_t)(row*HG_PB + c*8)*2u,
                 Bg + (size_t)(kt*HG_BK + row)*ldb + c*8);
        }
        asm volatile("cp.async.commit_group;\n");
    };

    auto compute = [&](int s){
        const uint32_t ab = shb + (uint32_t)(s*HG_STG)*2u;
        const uint32_t bb = ab + (uint32_t)(128*HG_PA)*2u;
        #pragma unroll
        for (int ks=0; ks<HG_BK/16; ks++){
            uint32_t af[4][4], bf[4][4];
            #pragma unroll
            for (int mf=0; mf<4; mf++){
                int row  = wm*64 + mf*16 + (lane & 15);
                int colh = ks*16 + ((lane>>4)<<3);
                ldsm4(af[mf], ab + (uint32_t)(row*HG_PA + colh)*2u);
            }
            #pragma unroll
            for (int nh=0; nh<4; nh++){
                int row = ks*16 + (lane & 15);
                int col = wn*64 + nh*16 + ((lane>>4)<<3);
                ldsm4t(bf[nh], bb + (uint32_t)(row*HG_PB + col)*2u);
            }
            #pragma unroll
            for (int mf=0; mf<4; mf++)
                #pragma unroll
                for (int nf=0; nf<8; nf++)
                    mma_f16(acc[mf][nf], af[mf], &bf[nf>>1][(nf&1)*2]);
        }
    };

    const int KT = K / HG_BK;
    load_stage(0,0); load_stage(1,1);

    #pragma unroll 1
    for (int kt=0; kt<KT; kt++){
        if (kt+1 < KT) asm volatile("cp.async.wait_group 1;\n");
        else           asm volatile("cp.async.wait_group 0;\n");
        __syncthreads();                 // stage kt resident; stage (kt+2)%3 free
        if (kt+2 < KT){
            int s = (kt+2) % 3;
            load_stage(kt+2, s);
        }
        compute(kt % 3);
    }

    if constexpr (EPI == 0){
        __half* Cg = (__half*)Cgp + b*strC + (size_t)mt*128*ldc + (size_t)nt*HG_BN;
        #pragma unroll
        for (int mf=0; mf<4; mf++){
            int r = wm*64 + mf*16 + grp;
            #pragma unroll
            for (int nf=0; nf<8; nf++){
                int c = wn*64 + nf*8 + tig*2;
                *(__half2*)(Cg + (size_t)r*ldc + c) =
                    __floats2half2_rn(acc[mf][nf][0], acc[mf][nf][1]);
                *(__half2*)(Cg + (size_t)(r+8)*ldc + c) =
                    __floats2half2_rn(acc[mf][nf][2], acc[mf][nf][3]);
            }
        }
    } else {
        float* Cg = (float*)Cgp + b*strC + (size_t)mt*128*ldc + (size_t)nt*HG_BN;
        const float* ivp = invs + b*SEQ + mt*128;
        #pragma unroll
        for (int mf=0; mf<4; mf++){
            int r = wm*64 + mf*16 + grp;
            float s0 = ivp[r], s1 = ivp[r+8];
            #pragma unroll
            for (int nf=0; nf<8; nf++){
                int c = wn*64 + nf*8 + tig*2;
                float2 v0, v1;
                v0.x = acc[mf][nf][0]*s0; v0.y = acc[mf][nf][1]*s0;
                v1.x = acc[mf][nf][2]*s1; v1.y = acc[mf][nf][3]*s1;
                *(float2*)(Cg + (size_t)r*ldc + c)     = v0;
                *(float2*)(Cg + (size_t)(r+8)*ldc + c) = v1;
            }
        }
    }
}

// ---------------------------------------------------------------------------
// E = exp(scores) (fp16, unnormalized) + per-tile rowsum partials.
// ---------------------------------------------------------------------------
__global__ void __launch_bounds__(256,1)
scores_exp(const float* __restrict__ xqk, __half* __restrict__ E,
           float* __restrict__ part)
{
    constexpr int PA = 36;
    __shared__ float sQ[128*PA];
    __shared__ float sK[128*PA];
    __shared__ float spart[4][128];

    const int b = blockIdx.z, qt = blockIdx.y, nt = blockIdx.x;
    const int tid = threadIdx.x, warp = tid>>5, lane = tid&31;
    const int wm = warp>>2, wn = warp&3, grp = lane>>2, tig = lane&3;

    const uint32_t sQb = (uint32_t)__cvta_generic_to_shared(sQ);
    const uint32_t sKb = (uint32_t)__cvta_generic_to_shared(sK);

    const int lr = tid>>3, lc = (tid&7)*4;
    const float* Qg = xqk + ((size_t)b*SEQ + qt*128)*64;
    const float* Kg = xqk + ((size_t)b*SEQ + nt*128)*64 + 32;
    #pragma unroll
    for (int p=0;p<4;p++){
        int r = lr + p*32;
        cp16(sQb + (uint32_t)(r*PA + lc)*4u, Qg + (size_t)r*64 + lc);
        cp16(sKb + (uint32_t)(r*PA + lc)*4u, Kg + (size_t)r*64 + lc);
    }
    asm volatile("cp.async.commit_group;\n");
    asm volatile("cp.async.wait_group 0;\n");
    __syncthreads();

    float acc[4][4][4];
    #pragma unroll
    for (int i=0;i<4;i++)
        #pragma unroll
        for (int j=0;j<4;j++)
            #pragma unroll
            for (int q=0;q<4;q++) acc[i][j][q]=0.f;

    #pragma unroll
    for (int k8=0;k8<4;k8++){
        uint32_t af[4][4], bf[4][2];
        #pragma unroll
        for (int mf=0;mf<4;mf++){
            int r = wm*64 + mf*16 + grp;
            const float* base = sQ + r*PA + k8*8 + tig;
            af[mf][0]=__float_as_uint(base[0]);
            af[mf][1]=__float_as_uint(base[8*PA]);
            af[mf][2]=__float_as_uint(base[4]);
            af[mf][3]=__float_as_uint(base[8*PA+4]);
        }
        #pragma unroll
        for (int nf=0;nf<4;nf++){
            int n = wn*32 + nf*8 + grp;
            const float* base = sK + n*PA + k8*8 + tig;
            bf[nf][0]=__float_as_uint(base[0]);
            bf[nf][1]=__float_as_uint(base[4]);
        }
        #pragma unroll
        for (int mf=0;mf<4;mf++)
            #pragma unroll
            for (int nf=0;nf<4;nf++)
                mma_tf32(acc[mf][nf], af[mf], bf[nf]);
    }

    const float isc = 1.0f/32.0f;
    float rs[4][2];
    #pragma unroll
    for (int mf=0;mf<4;mf++){ rs[mf][0]=0.f; rs[mf][1]=0.f; }

    #pragma unroll
    for (int mf=0;mf<4;mf++){
        int r = wm*64 + mf*16 + grp;
        size_t rowo = ((size_t)b*SEQ + qt*128 + r)*SEQ + nt*128;
        #pragma unroll
        for (int nf=0;nf<4;nf++){
            int c = wn*32 + nf*8 + tig*2;
            float e0 = __expf(acc[mf][nf][0]*isc);
            float e1 = __expf(acc[mf][nf][1]*isc);
            float e2 = __expf(acc[mf][nf][2]*isc);
            float e3 = __expf(acc[mf][nf][3]*isc);
            __half2 h0 = __floats2half2_rn(e0,e1);
            __half2 h1 = __floats2half2_rn(e2,e3);
            *(__half2*)&E[rowo + c]         = h0;
            *(__half2*)&E[rowo + 8*SEQ + c] = h1;
            float2 f0 = __half22float2(h0);
            float2 f1 = __half22float2(h1);
            rs[mf][0] += f0.x + f0.y;
            rs[mf][1] += f1.x + f1.y;
        }
    }
    #pragma unroll
    for (int mf=0;mf<4;mf++){
        #pragma unroll
        for (int j=0;j<2;j++){
            float v = rs[mf][j];
            v += __shfl_xor_sync(0xffffffffu, v, 1);
            v += __shfl_xor_sync(0xffffffffu, v, 2);
            if (tig==0) spart[wn][wm*64 + mf*16 + grp + j*8] = v;
        }
    }
    __syncthreads();
    if (tid < 128){
        float s = spart[0][tid] + spart[1][tid] + spart[2][tid] + spart[3][tid];
        part[((size_t)b*SEQ + qt*128 + tid)*(SEQ/128) + nt] = s;
    }
}

__global__ void __launch_bounds__(256) invs_kernel(const float* __restrict__ part,
                                                   float* __restrict__ invs){
    int r = blockIdx.x*blockDim.x + threadIdx.x;
    const float* p = part + (size_t)r*(SEQ/128);
    float s = 0.f;
    #pragma unroll
    for (int i=0;i<SEQ/128;i++) s += p[i];
    invs[r] = 1.0f/s;
}

extern "C" void kernel_launch(void* const* d_in, const int* in_sizes, int n_in,
                              void* d_out, int out_size){
    const float* x  = (const float*)d_in[0];
    const float* Q  = (const float*)d_in[1];
    const float* Km = (const float*)d_in[2];
    const float* VO = (const float*)d_in[3];
    float* out = (float*)d_out;

    float *xr, *qk, *xqk, *part, *invs;
    __half *xh, *voh, *wh, *E;
    cudaGetSymbolAddress((void**)&xr,   g_xr);
    cudaGetSymbolAddress((void**)&xh,   g_xh);
    cudaGetSymbolAddress((void**)&qk,   g_qk);
    cudaGetSymbolAddress((void**)&voh,  g_voh);
    cudaGetSymbolAddress((void**)&xqk,  g_xqk);
    cudaGetSymbolAddress((void**)&wh,   g_wh);
    cudaGetSymbolAddress((void**)&E,    g_E);
    cudaGetSymbolAddress((void**)&part, g_part);
    cudaGetSymbolAddress((void**)&invs, g_invs);

    // No static guard (harness forbids them); these are idempotent host calls.
    cudaFuncSetAttribute(hgemm<0>, cudaFuncAttributeMaxDynamicSharedMemorySize, HG_SMEM);
    cudaFuncSetAttribute(hgemm<1>, cudaFuncAttributeMaxDynamicSharedMemorySize, HG_SMEM);

    // 1) Rounding passes: x -> (tf32 f32, fp16) in one read; Q,K tf32; VO fp16
    round_both  <<<2048,256>>>(x, xr, xh, BATCH*SEQ*DIM/4);
    round_kernel<<<32,  256>>>(Q,  qk,             RANK*DIM/4);
    round_kernel<<<32,  256>>>(Km, qk + RANK*DIM,  RANK*DIM/4);
    round_half  <<<512, 256>>>(VO, voh, DIM*DIM/4);

    // 2) Projections: xqk[16384,64] = x @ [Q;K]^T  (tf32 NT)
    gemm_tf32_nt<128,64,16><<<dim3(1,128,1),256>>>(xr, qk, xqk, DIM, DIM, DIM, 64);

    // 3) w[b,u,e] = x[b,u,:] @ VO   (fp16 multistage NN, fp16 out)
    hgemm<0><<<dim3(DIM/HG_BN, SEQ/128, BATCH), 256, HG_SMEM>>>(
        xh, voh, wh, nullptr, DIM, DIM, DIM, DIM,
        (size_t)SEQ*DIM, 0, (size_t)SEQ*DIM);

    // 4) E = exp(xq@xk^T / 32), fp16, unnormalized + rowsum partials
    scores_exp<<<dim3(SEQ/128, SEQ/128, BATCH),256>>>(xqk, E, part);

    // 5) invs = 1 / rowsum
    invs_kernel<<<BATCH*SEQ/256,256>>>(part, invs);

    // 6) out = invs ⊙ (E @ w)  (fp16 multistage NN, f32 out with row scaling)
    hgemm<1><<<dim3(DIM/HG_BN, SEQ/128, BATCH), 256, HG_SMEM>>>(
        E, wh, out, invs, SEQ, SEQ, DIM, DIM,
        (size_t)SEQ*SEQ, (size_t)SEQ*DIM, (size_t)SEQ*DIM);
}